// round 3
// baseline (speedup 1.0000x reference)
#include <cuda_runtime.h>

// ThinVesselLoss: EDT only matters through thin = (0 < 2*dist < 3)
// <=> D2 in {1,2} <=> foreground pixel with >=1 in-bounds 8-neighbor
// background pixel. So: 3x3 stencil on (target > 0.5) + weighted BCE + mean.
//
// Latency-bound problem (1M px): each warp owns one 512-px row and
// front-batches ALL its loads (pred row + 3 target rows = 16 LDG.128)
// for maximal MLP. No inter-warp sharing, no barrier in the load path.
// Fused finalize via atomic ticket: last block reduces the partials.

#define B_N 4
#define H_N 512
#define W_N 512
#define NPIX (B_N * H_N * W_N)
#define WARPS_PER_BLOCK 4
#define NTHREADS (WARPS_PER_BLOCK * 32)              // 128
#define NBLOCKS ((B_N * H_N) / WARPS_PER_BLOCK)      // 512

__device__ float g_partial[NBLOCKS];
__device__ unsigned g_ticket;   // zero-init; last block resets to 0

__device__ __forceinline__ unsigned mask16(const float4* r4) {
    unsigned m = 0u;
#pragma unroll
    for (int ch = 0; ch < 4; ch++) {
        float4 v = r4[ch];
        m |= (unsigned)(v.x <= 0.5f) << (4 * ch + 0);
        m |= (unsigned)(v.y <= 0.5f) << (4 * ch + 1);
        m |= (unsigned)(v.z <= 0.5f) << (4 * ch + 2);
        m |= (unsigned)(v.w <= 0.5f) << (4 * ch + 3);
    }
    return m;
}

__global__ void __launch_bounds__(NTHREADS)
tv_fused(const float* __restrict__ pred, const float* __restrict__ tgt,
         float* __restrict__ out) {
    const int w    = threadIdx.x >> 5;
    const int lane = threadIdx.x & 31;
    const int row  = blockIdx.x * WARPS_PER_BLOCK + w;   // 0..2047
    const int b    = row >> 9;
    const int y    = row & (H_N - 1);
    const long imgbase = (long)b * (H_N * W_N);
    const int  colbase = lane * 16;

    // Clamped row indices so halo loads are always valid (masks zeroed below).
    const int ym = (y > 0)         ? y - 1 : 0;
    const int yp = (y < H_N - 1)   ? y + 1 : H_N - 1;

    const float4* pc = reinterpret_cast<const float4*>(pred + imgbase + (long)y  * W_N + colbase);
    const float4* tc = reinterpret_cast<const float4*>(tgt  + imgbase + (long)y  * W_N + colbase);
    const float4* ta = reinterpret_cast<const float4*>(tgt  + imgbase + (long)ym * W_N + colbase);
    const float4* tb = reinterpret_cast<const float4*>(tgt  + imgbase + (long)yp * W_N + colbase);

    // ---- front-batch ALL 16 LDG.128 (maximal MLP, one latency exposure) ----
    float4 P[4], C[4], A[4], Bv[4];
#pragma unroll
    for (int ch = 0; ch < 4; ch++) P[ch]  = __ldg(pc + ch);
#pragma unroll
    for (int ch = 0; ch < 4; ch++) C[ch]  = __ldg(tc + ch);
#pragma unroll
    for (int ch = 0; ch < 4; ch++) A[ch]  = __ldg(ta + ch);
#pragma unroll
    for (int ch = 0; ch < 4; ch++) Bv[ch] = __ldg(tb + ch);

    // ---- background masks ----
    unsigned mC = mask16(C);
    unsigned mA = (y > 0)         ? mask16(A)  : 0u;
    unsigned mB = (y < H_N - 1)   ? mask16(Bv) : 0u;
    unsigned M  = mC | mA | mB;

    // horizontal halo via shuffle; image edges contribute no background
    unsigned left  = __shfl_up_sync(0xffffffffu, M, 1);
    unsigned right = __shfl_down_sync(0xffffffffu, M, 1);
    if (lane == 0)  left  = 0u;
    if (lane == 31) right = 0u;
    unsigned mExt = (M << 1) | ((left >> 15) & 1u) | ((right & 1u) << 17);

    // ---- weighted BCE ----
    float acc = 0.0f;
#pragma unroll
    for (int ch = 0; ch < 4; ch++) {
        float pv[4] = {P[ch].x, P[ch].y, P[ch].z, P[ch].w};
        float tv[4] = {C[ch].x, C[ch].y, C[ch].z, C[ch].w};
#pragma unroll
        for (int k = 0; k < 4; k++) {
            const int i = 4 * ch + k;
            const float t  = tv[k];
            const float lp = fmaxf(__logf(pv[k]),        -100.0f);
            const float lq = fmaxf(__logf(1.0f - pv[k]), -100.0f);
            const float bce = -(t * lp + (1.0f - t) * lq);
            const bool thin = (t > 0.5f) && (((mExt >> i) & 7u) != 0u);
            acc += thin ? 3.0f * bce : bce;
        }
    }

    // ---- block reduction ----
#pragma unroll
    for (int off = 16; off > 0; off >>= 1)
        acc += __shfl_xor_sync(0xffffffffu, acc, off);

    __shared__ float ws[WARPS_PER_BLOCK];
    __shared__ bool amLast;
    if (lane == 0) ws[w] = acc;
    __syncthreads();
    if (threadIdx.x == 0) {
        float s = 0.0f;
#pragma unroll
        for (int i = 0; i < WARPS_PER_BLOCK; i++) s += ws[i];
        g_partial[blockIdx.x] = s;
        __threadfence();
        unsigned t = atomicAdd(&g_ticket, 1u);
        amLast = (t == (unsigned)(gridDim.x - 1));
    }
    __syncthreads();

    // ---- last block: reduce NBLOCKS partials (128 thr x 1 float4 each) ----
    if (amLast) {
        const float4* p4 = reinterpret_cast<const float4*>(g_partial);
        float4 v4 = __ldcg(&p4[threadIdx.x]);   // NBLOCKS/4 == NTHREADS
        double v = (double)v4.x + (double)v4.y + (double)v4.z + (double)v4.w;
#pragma unroll
        for (int off = 16; off > 0; off >>= 1)
            v += __shfl_xor_sync(0xffffffffu, v, off);
        __shared__ double ds[WARPS_PER_BLOCK];
        if (lane == 0) ds[w] = v;
        __syncthreads();
        if (threadIdx.x == 0) {
            double s = 0.0;
#pragma unroll
            for (int i = 0; i < WARPS_PER_BLOCK; i++) s += ds[i];
            out[0] = (float)(s / (double)NPIX);
            g_ticket = 0u;  // reset for next graph replay
        }
    }
}

extern "C" void kernel_launch(void* const* d_in, const int* in_sizes, int n_in,
                              void* d_out, int out_size) {
    const float* pred = (const float*)d_in[0];
    const float* tgt  = (const float*)d_in[1];
    float* out = (float*)d_out;
    (void)in_sizes; (void)n_in; (void)out_size;

    tv_fused<<<NBLOCKS, NTHREADS>>>(pred, tgt, out);
}